// round 15
// baseline (speedup 1.0000x reference)
#include <cuda_runtime.h>
#include <cuda_bf16.h>
#include <math.h>
#include <stdint.h>

#define BB 256
#define LL 200
#define DD 512
#define BBDD (BB * DD)
typedef uint32_t u32;

// ---------------- fp32 scratch ----------------
__device__ float g_xproj[(size_t)BB * LL * 3 * DD];   // [B,L,3D] (+bih)
__device__ float g_sseq [(size_t)LL * BB * DD];       // [L,B,D]
__device__ float g_rx   [(size_t)LL * BB * DD];
__device__ float g_ux   [(size_t)LL * BB * DD];
__device__ float g_nx   [(size_t)LL * BB * DD];
__device__ float g_u    [BB * DD];
__device__ float g_logits[LL * BB];
__device__ float g_att   [LL * BB];
__device__ float g_ue    [BB * DD];
__device__ float g_hf    [2 * BB * DD];
__device__ float g_zero  [BB * DD];                   // fp32 zeros == packed zeros

// ---------------- packed (bf16-pair) activations ----------------
__device__ u32 g_Psess[(size_t)BB * LL * DD];
__device__ u32 g_Ptar [BB * DD];
__device__ u32 g_Psseq[(size_t)LL * BB * DD];
__device__ u32 g_Phr  [BB * DD];
__device__ u32 g_Pp   [2 * BB * DD];

// ---------------- weight fragments (B-operand order) ----------------
__device__ u32 g_Fwih[1536 * DD];
__device__ u32 g_Fwhh[1536 * DD];
__device__ u32 g_Fw  [DD * DD];
__device__ u32 g_Frh [DD * DD];
__device__ u32 g_Fuh [DD * DD];
__device__ u32 g_Fhh [DD * DD];
__device__ u32 g_Frx [DD * DD];
__device__ u32 g_Fux [DD * DD];
__device__ u32 g_Fhx [DD * DD];

// per-row-group barriers (4 groups of 32 blocks, counters padded)
__device__ unsigned int          g_gcnt[4 * 32];
__device__ volatile unsigned int g_ggen[4 * 32];

__device__ __forceinline__ float sigf(float x) { return 1.0f / (1.0f + __expf(-x)); }

__device__ __forceinline__ u32 packbf(float x) {
    __nv_bfloat16 hi = __float2bfloat16(x);
    float hf = __bfloat162float(hi);
    __nv_bfloat16 lo = __float2bfloat16(x - hf);
    return (u32)__bfloat16_as_ushort(hi) | ((u32)__bfloat16_as_ushort(lo) << 16);
}

__device__ __forceinline__ void pf2(const void* p) {
    asm volatile("prefetch.global.L2 [%0];" :: "l"(p));
}

// 32-block barrier over one row group
__device__ __forceinline__ void group_barrier(int mi) {
    __syncthreads();
    if (threadIdx.x == 0) {
        __threadfence();
        unsigned int gen = g_ggen[mi * 32];
        unsigned int old = atomicAdd(&g_gcnt[mi * 32], 1u);
        if (old == 31u) {
            atomicExch(&g_gcnt[mi * 32], 0u);
            __threadfence();
            atomicAdd((unsigned int*)&g_ggen[mi * 32], 1u);
        } else {
            while (g_ggen[mi * 32] == gen) { }
        }
        __threadfence();
    }
    __syncthreads();
}

__device__ __forceinline__ void mma16(float* d, const u32* a, u32 b0, u32 b1) {
    asm volatile(
        "mma.sync.aligned.m16n8k16.row.col.f32.bf16.bf16.f32 "
        "{%0,%1,%2,%3},{%4,%5,%6,%7},{%8,%9},{%0,%1,%2,%3};"
        : "+f"(d[0]), "+f"(d[1]), "+f"(d[2]), "+f"(d[3])
        : "r"(a[0]), "r"(a[1]), "r"(a[2]), "r"(a[3]), "r"(b0), "r"(b1));
}

// ==================================================================
// 256-thread 128x64 core (unchanged — proven) for the big GEMMs
// ==================================================================
struct MMSmem { u32 A[2][16][136]; };

__device__ __forceinline__ void mm_core(
    MMSmem* sm, const u32* __restrict__ Ap,
    const u32* __restrict__ F, int gnt0,
    float acc[2][4][4])
{
    const int tid  = threadIdx.x;
    const int lane = tid & 31;
    const int gq = lane >> 2, tq = lane & 3;
    const int w  = tid >> 5;
    const int wm = w >> 1, wn = w & 1;
    const int r  = tid >> 1, h = tid & 1;

    const u32* arow = Ap + (size_t)r * DD + h * 8;

    uint4 bv[4], nbv[4], na0, na1;

    uint4 va0 = *(const uint4*)(arow + 0);
    uint4 va1 = *(const uint4*)(arow + 4);
    #pragma unroll
    for (int nt = 0; nt < 4; nt++) {
        int gnt = gnt0 + wn * 4 + nt;
        bv[nt] = *(const uint4*)(F + (((size_t)gnt * 32 + 0) * 32 + lane) * 4);
    }
    {
        u32 e0[4] = {va0.x, va0.y, va0.z, va0.w};
        u32 e1[4] = {va1.x, va1.y, va1.z, va1.w};
        #pragma unroll
        for (int j = 0; j < 4; j++) {
            int jj = (j + 2 * h) & 3;
            sm->A[0][h * 8 + 0 + jj][r] = e0[jj];
            sm->A[0][h * 8 + 4 + jj][r] = e1[jj];
        }
    }
    __syncthreads();

    #pragma unroll 1
    for (int s2 = 0; s2 < 32; s2++) {
        const int buf = s2 & 1;
        if (s2 < 31) {
            const u32* ar = arow + (s2 + 1) * 16;
            na0 = *(const uint4*)(ar);
            na1 = *(const uint4*)(ar + 4);
            #pragma unroll
            for (int nt = 0; nt < 4; nt++) {
                int gnt = gnt0 + wn * 4 + nt;
                nbv[nt] = *(const uint4*)(F + (((size_t)gnt * 32 + (s2 + 1)) * 32 + lane) * 4);
            }
        }
        #pragma unroll
        for (int sl = 0; sl < 2; sl++) {
            u32 a[2][4], as[2][4];
            #pragma unroll
            for (int mt = 0; mt < 2; mt++) {
                int rb = wm * 32 + mt * 16 + gq;
                a[mt][0] = sm->A[buf][sl * 8 + tq][rb];
                a[mt][1] = sm->A[buf][sl * 8 + tq][rb + 8];
                a[mt][2] = sm->A[buf][sl * 8 + tq + 4][rb];
                a[mt][3] = sm->A[buf][sl * 8 + tq + 4][rb + 8];
                #pragma unroll
                for (int q = 0; q < 4; q++)
                    as[mt][q] = __funnelshift_l(a[mt][q], a[mt][q], 16);
            }
            #pragma unroll
            for (int nt = 0; nt < 4; nt++) {
                u32 b0 = sl ? bv[nt].z : bv[nt].x;
                u32 b1 = sl ? bv[nt].w : bv[nt].y;
                #pragma unroll
                for (int mt = 0; mt < 2; mt++) {
                    mma16(acc[mt][nt], a[mt],  b0, b1);
                    mma16(acc[mt][nt], as[mt], b0, b1);
                }
            }
        }
        if (s2 < 31) {
            u32 e0[4] = {na0.x, na0.y, na0.z, na0.w};
            u32 e1[4] = {na1.x, na1.y, na1.z, na1.w};
            #pragma unroll
            for (int j = 0; j < 4; j++) {
                int jj = (j + 2 * h) & 3;
                sm->A[buf ^ 1][h * 8 + 0 + jj][r] = e0[jj];
                sm->A[buf ^ 1][h * 8 + 4 + jj][r] = e1[jj];
            }
            #pragma unroll
            for (int nt = 0; nt < 4; nt++) bv[nt] = nbv[nt];
        }
        __syncthreads();
    }
}

__global__ __launch_bounds__(256) void mm_big(
    const u32* __restrict__ Ap,
    const u32* __restrict__ F,
    const float* __restrict__ bias,
    float* __restrict__ C, int ldc)
{
    __shared__ MMSmem sm;
    const int bm = blockIdx.x * 128, bn = blockIdx.y * 64;
    float acc[2][4][4];
    #pragma unroll
    for (int i = 0; i < 2; i++)
        #pragma unroll
        for (int j = 0; j < 4; j++)
            #pragma unroll
            for (int e = 0; e < 4; e++) acc[i][j][e] = 0.f;
    mm_core(&sm, Ap + (size_t)bm * DD, F, bn >> 3, acc);

    const int lane = threadIdx.x & 31;
    const int gq = lane >> 2, tq = lane & 3;
    const int w = threadIdx.x >> 5;
    const int wm = w >> 1, wn = w & 1;
    #pragma unroll
    for (int mt = 0; mt < 2; mt++)
        #pragma unroll
        for (int nt = 0; nt < 4; nt++) {
            int row = bm + wm * 32 + mt * 16 + gq;
            int col = bn + wn * 32 + nt * 8 + 2 * tq;
            float b0 = bias ? bias[col] : 0.f;
            float b1 = bias ? bias[col + 1] : 0.f;
            *(float2*)(C + (size_t)row * ldc + col) =
                make_float2(acc[mt][nt][0] + b0, acc[mt][nt][1] + b1);
            *(float2*)(C + (size_t)(row + 8) * ldc + col) =
                make_float2(acc[mt][nt][2] + b0, acc[mt][nt][3] + b1);
        }
}

// ==================================================================
// SMEM-resident-weight recurrence core: 64 rows x 16 cols x NG gates
// 512 threads = 4 m-tiles x 4 k-quarters. Dynamic smem:
//   Wsm [NG*8192 u32]  (weights, persistent across steps)
//   Asm [64][516 u32]  (A tile, stride 516 => frag banks 4*gq+tq)
//   Red overlays Asm
// ==================================================================
#define WSM_WORDS 24576
#define ASM_WORDS (64 * 516)
#define DSMEM_BYTES ((WSM_WORDS + ASM_WORDS) * 4)

template<int NG>
__device__ __forceinline__ void rec_coreS(
    const u32* Wsm, u32* Asm, float* Red,
    const u32* __restrict__ Ap,
    float acc[NG][2][4])
{
    const int tid  = threadIdx.x;
    const int lane = tid & 31;
    const int gq = lane >> 2, tq = lane & 3;
    const int w  = tid >> 5;
    const int wk = w >> 2, wm = w & 3;

    // A tile load: thread t -> row t&63, 16 uint4 slice (conflict-free STS)
    {
        const int r = tid & 63, s = tid >> 6;
        const uint4* src = (const uint4*)(Ap + (size_t)r * DD) + s * 16;
        uint4* dst = (uint4*)(Asm + r * 516) + s * 16;
        #pragma unroll
        for (int j = 0; j < 16; j++) dst[j] = src[j];
    }
    __syncthreads();

    const int r0 = wm * 16 + gq;
    const u32* arow0 = Asm + r0 * 516 + wk * 128;
    const u32* arow1 = Asm + (r0 + 8) * 516 + wk * 128;

    #pragma unroll 2
    for (int s2 = 0; s2 < 8; s2++) {
        uint4 bq[NG][2];
        #pragma unroll
        for (int g = 0; g < NG; g++)
            #pragma unroll
            for (int nt = 0; nt < 2; nt++)
                bq[g][nt] = *(const uint4*)(Wsm + g * 8192 +
                    ((nt * 32 + wk * 8 + s2) * 32 + lane) * 4);
        #pragma unroll
        for (int sl = 0; sl < 2; sl++) {
            const int kb = s2 * 16 + sl * 8;
            u32 a[4], as[4];
            a[0] = arow0[kb + tq];
            a[1] = arow1[kb + tq];
            a[2] = arow0[kb + tq + 4];
            a[3] = arow1[kb + tq + 4];
            #pragma unroll
            for (int q = 0; q < 4; q++) as[q] = __funnelshift_l(a[q], a[q], 16);
            #pragma unroll
            for (int g = 0; g < NG; g++)
                #pragma unroll
                for (int nt = 0; nt < 2; nt++) {
                    u32 b0 = sl ? bq[g][nt].z : bq[g][nt].x;
                    u32 b1 = sl ? bq[g][nt].w : bq[g][nt].y;
                    mma16(acc[g][nt], a,  b0, b1);
                    mma16(acc[g][nt], as, b0, b1);
                }
        }
    }
    __syncthreads();   // A dead; Red overlays

    const int stride = NG * 8 + 1;
    if (wk) {
        int base = (tid - 128) * stride;
        #pragma unroll
        for (int g = 0; g < NG; g++)
            #pragma unroll
            for (int nt = 0; nt < 2; nt++)
                #pragma unroll
                for (int e = 0; e < 4; e++)
                    Red[base + (g * 2 + nt) * 4 + e] = acc[g][nt][e];
    }
    __syncthreads();
    if (!wk) {
        #pragma unroll
        for (int k = 0; k < 3; k++) {
            int base = (k * 128 + tid) * stride;
            #pragma unroll
            for (int g = 0; g < NG; g++)
                #pragma unroll
                for (int nt = 0; nt < 2; nt++)
                    #pragma unroll
                    for (int e = 0; e < 4; e++)
                        acc[g][nt][e] += Red[base + (g * 2 + nt) * 4 + e];
        }
    }
}

// ---------------- persistent GRU: 4 row-groups x 32 col-blocks ----------------
__global__ __launch_bounds__(512) void gru3(
    const float* __restrict__ zero, const u32* __restrict__ Pzero,
    const u32* __restrict__ Fwhh, const float* __restrict__ bhh,
    const float* __restrict__ xproj,
    float* __restrict__ sseq, u32* __restrict__ Psseq)
{
    extern __shared__ u32 dyn[];
    u32* Wsm = dyn;
    u32* Asm = dyn + WSM_WORDS;
    float* Red = (float*)Asm;

    const int blk = blockIdx.x;
    const int mi = blk >> 5, di = blk & 31;
    const int bm = mi * 64;
    const int tid = threadIdx.x;
    const int lane = tid & 31;
    const int gq = lane >> 2, tq = lane & 3;
    const int w = tid >> 5;
    const int wm = w & 3;

    // preload weights (3 gates x 16 cols): contiguous fragment slices
    #pragma unroll
    for (int g = 0; g < 3; g++) {
        const uint4* src = (const uint4*)(Fwhh + (size_t)(g * 64 + di * 2) * 4096);
        uint4* dst = (uint4*)(Wsm + g * 8192);
        for (int i = tid; i < 2048; i += 512) dst[i] = src[i];
    }

    float bh[3][2][2];
    #pragma unroll
    for (int g = 0; g < 3; g++)
        #pragma unroll
        for (int nt = 0; nt < 2; nt++) {
            int col = di * 16 + nt * 8 + 2 * tq;
            bh[g][nt][0] = bhh[g * 512 + col];
            bh[g][nt][1] = bhh[g * 512 + col + 1];
        }

    for (int l = 0; l < LL; l++) {
        const u32* Ap = (l ? Psseq + (size_t)(l - 1) * BBDD : Pzero) + (size_t)bm * DD;
        const float* hprev = l ? sseq + (size_t)(l - 1) * BBDD : zero;

        if (tid < 128) {   // prefetch epilogue lines (overlaps GEMM)
            int colp = di * 16;
            #pragma unroll
            for (int half = 0; half < 2; half++) {
                int row = bm + wm * 16 + gq + half * 8;
                const float* xb = xproj + ((size_t)row * LL + l) * 1536 + colp;
                pf2(xb); pf2(xb + 512); pf2(xb + 1024);
                pf2(hprev + (size_t)row * DD + colp);
            }
        }

        float acc[3][2][4];
        #pragma unroll
        for (int g = 0; g < 3; g++)
            #pragma unroll
            for (int nt = 0; nt < 2; nt++)
                #pragma unroll
                for (int e = 0; e < 4; e++) acc[g][nt][e] = 0.f;

        rec_coreS<3>(Wsm, Asm, Red, Ap, acc);

        if (tid < 128) {
            float* sl_ = sseq + (size_t)l * BBDD;
            u32* pl = Psseq + (size_t)l * BBDD;
            #pragma unroll
            for (int nt = 0; nt < 2; nt++) {
                int col = di * 16 + nt * 8 + 2 * tq;
                #pragma unroll
                for (int half = 0; half < 2; half++) {
                    int row = bm + wm * 16 + gq + half * 8;
                    const float* xb = xproj + ((size_t)row * LL + l) * 1536;
                    size_t ix = (size_t)row * DD + col;
                    #pragma unroll
                    for (int c = 0; c < 2; c++) {
                        int e = half * 2 + c;
                        float rr = sigf(xb[col + c] + acc[0][nt][e] + bh[0][nt][c]);
                        float zz = sigf(xb[512 + col + c] + acc[1][nt][e] + bh[1][nt][c]);
                        float nn = tanhf(xb[1024 + col + c] + rr * (acc[2][nt][e] + bh[2][nt][c]));
                        float h0 = hprev[ix + c];
                        float hn = nn + zz * (h0 - nn);
                        sl_[ix + c] = hn;
                        pl[ix + c] = packbf(hn);
                    }
                }
            }
        }

        group_barrier(mi);
    }
}

// ---------------- persistent AUGRU: same decomposition ----------------
__global__ __launch_bounds__(512) void augru3(
    const float* __restrict__ hlast, const u32* __restrict__ Pinit,
    const u32* __restrict__ Frh, const u32* __restrict__ Fuh, const u32* __restrict__ Fhh,
    const float* __restrict__ rx, const float* __restrict__ ux, const float* __restrict__ nx,
    const float* __restrict__ att,
    float* __restrict__ hf, u32* __restrict__ Pp,
    u32* __restrict__ Phr, float* __restrict__ ue,
    float* __restrict__ out)
{
    extern __shared__ u32 dyn[];
    u32* Wsm = dyn;
    u32* Asm = dyn + WSM_WORDS;
    float* Red = (float*)Asm;

    const int blk = blockIdx.x;
    const int mi = blk >> 5, di = blk & 31;
    const int bm = mi * 64;
    const int tid = threadIdx.x;
    const int lane = tid & 31;
    const int gq = lane >> 2, tq = lane & 3;
    const int w = tid >> 5;
    const int wm = w & 3;

    {   // preload: slot0=Frh, slot1=Fuh, slot2=Fhh (h-halves, 16 cols each)
        const u32* srcs[3] = {Frh, Fuh, Fhh};
        #pragma unroll
        for (int g = 0; g < 3; g++) {
            const uint4* src = (const uint4*)(srcs[g] + (size_t)(di * 2) * 4096);
            uint4* dst = (uint4*)(Wsm + g * 8192);
            for (int i = tid; i < 2048; i += 512) dst[i] = src[i];
        }
    }

    for (int l = 0; l < LL; l++) {
        const float* hc = l ? hf + (size_t)(l & 1) * BBDD : hlast;
        const u32* Pc = l ? Pp + (size_t)(l & 1) * BBDD : Pinit;

        {   // phase A: r and u_eff
            if (tid < 128) {
                int colp = di * 16;
                const float* rxl = rx + (size_t)l * BBDD;
                const float* uxl = ux + (size_t)l * BBDD;
                const float* nxl = nx + (size_t)l * BBDD;
                #pragma unroll
                for (int half = 0; half < 2; half++) {
                    int row = bm + wm * 16 + gq + half * 8;
                    size_t ixp = (size_t)row * DD + colp;
                    pf2(rxl + ixp); pf2(uxl + ixp); pf2(nxl + ixp);
                    pf2(hc + ixp);
                }
                pf2(att + (size_t)l * BB + bm);
            }

            float acc[2][2][4];
            #pragma unroll
            for (int g = 0; g < 2; g++)
                #pragma unroll
                for (int nt = 0; nt < 2; nt++)
                    #pragma unroll
                    for (int e = 0; e < 4; e++) acc[g][nt][e] = 0.f;

            rec_coreS<2>(Wsm, Asm, Red, Pc + (size_t)bm * DD, acc);

            if (tid < 128) {
                const float* rxl = rx + (size_t)l * BBDD;
                const float* uxl = ux + (size_t)l * BBDD;
                #pragma unroll
                for (int nt = 0; nt < 2; nt++) {
                    int col = di * 16 + nt * 8 + 2 * tq;
                    #pragma unroll
                    for (int half = 0; half < 2; half++) {
                        int row = bm + wm * 16 + gq + half * 8;
                        size_t ix = (size_t)row * DD + col;
                        float a = att[(size_t)l * BB + row];
                        #pragma unroll
                        for (int c = 0; c < 2; c++) {
                            int e = half * 2 + c;
                            float vr = acc[0][nt][e] + rxl[ix + c];
                            float vu = acc[1][nt][e] + uxl[ix + c];
                            Phr[ix + c] = packbf(hc[ix + c] * sigf(vr));
                            ue[ix + c]  = a * sigf(vu);
                        }
                    }
                }
            }
        }

        group_barrier(mi);

        {   // phase B: hhat + output update
            float acc[1][2][4];
            #pragma unroll
            for (int nt = 0; nt < 2; nt++)
                #pragma unroll
                for (int e = 0; e < 4; e++) acc[0][nt][e] = 0.f;

            rec_coreS<1>(Wsm + 2 * 8192, Asm, Red, Phr + (size_t)bm * DD, acc);

            if (tid < 128) {
                float* ho = (l == LL - 1) ? out : hf + (size_t)((l + 1) & 1) * BBDD;
                u32* Pn = Pp + (size_t)((l + 1) & 1) * BBDD;
                const float* nxl = nx + (size_t)l * BBDD;
                #pragma unroll
                for (int nt = 0; nt < 2; nt++) {
                    int col = di * 16 + nt * 8 + 2 * tq;
                    #pragma unroll
                    for (int half = 0; half < 2; half++) {
                        int row = bm + wm * 16 + gq + half * 8;
                        size_t ix = (size_t)row * DD + col;
                        #pragma unroll
                        for (int c = 0; c < 2; c++) {
                            int e = half * 2 + c;
                            float hh = tanhf(acc[0][nt][e] + nxl[ix + c]);
                            float h0 = hc[ix + c];
                            float u0 = ue[ix + c];
                            float hn = h0 + u0 * (hh - h0);
                            ho[ix + c] = hn;
                            Pn[ix + c] = packbf(hn);
                        }
                    }
                }
            }
        }

        group_barrier(mi);
    }
}

// ---------------- conversion kernels ----------------
__global__ void pack_zero_kernel(const float* __restrict__ x, u32* __restrict__ p, int n4,
                                 float* __restrict__ z, int zn4)
{
    int i = blockIdx.x * 256 + threadIdx.x;
    if (i < n4) {
        float4 v = ((const float4*)x)[i];
        uint4 o;
        o.x = packbf(v.x); o.y = packbf(v.y); o.z = packbf(v.z); o.w = packbf(v.w);
        ((uint4*)p)[i] = o;
    }
    if (i < zn4) ((float4*)z)[i] = make_float4(0.f, 0.f, 0.f, 0.f);
}

__global__ void pack_kernel(const float* __restrict__ x, u32* __restrict__ p, int n4)
{
    int i = blockIdx.x * 256 + threadIdx.x;
    if (i < n4) {
        float4 v = ((const float4*)x)[i];
        uint4 o;
        o.x = packbf(v.x); o.y = packbf(v.y); o.z = packbf(v.z); o.w = packbf(v.w);
        ((uint4*)p)[i] = o;
    }
}

__device__ __forceinline__ void wfrag_one(const float* W, int ldw, int woff,
                                          u32* F, int idx)
{
    int j = idx & 3, lane = (idx >> 2) & 31, s2 = (idx >> 7) & 31, gnt = idx >> 12;
    int g = lane >> 2, t = lane & 3;
    int sl = s2 * 2 + (j >> 1), b = j & 1;
    int ok = sl * 8 + t + 4 * b;
    int n = gnt * 8 + g;
    F[idx] = packbf(W[(size_t)n * ldw + woff + ok]);
}

__global__ void wfrag2_kernel(const float* __restrict__ W1, const float* __restrict__ W2,
                              u32* __restrict__ F1, u32* __restrict__ F2, int total)
{
    int idx0 = blockIdx.x * 256 + threadIdx.x;
    if (idx0 < total)               wfrag_one(W1, DD, 0, F1, idx0);
    else if (idx0 < 2 * total)      wfrag_one(W2, DD, 0, F2, idx0 - total);
}

__global__ void wfrag_kernel(const float* __restrict__ W, int ldw, int woff,
                             u32* __restrict__ F, int total)
{
    int idx = blockIdx.x * 256 + threadIdx.x;
    if (idx < total) wfrag_one(W, ldw, woff, F, idx);
}

// ---------------- attention ----------------
__global__ void attn_logits(const float* __restrict__ s, const float* __restrict__ u,
                            float* __restrict__ logits)
{
    int gw = (blockIdx.x * blockDim.x + threadIdx.x) >> 5;
    int lane = threadIdx.x & 31;
    int b = gw & (BB - 1);
    const float4* sr = (const float4*)(s + (size_t)gw * DD);
    const float4* ur = (const float4*)(u + (size_t)b * DD);
    float acc = 0.f;
    #pragma unroll
    for (int k = lane; k < DD / 4; k += 32) {
        float4 a = sr[k], c = ur[k];
        acc += a.x * c.x + a.y * c.y + a.z * c.z + a.w * c.w;
    }
    #pragma unroll
    for (int o = 16; o > 0; o >>= 1) acc += __shfl_xor_sync(0xffffffffu, acc, o);
    if (lane == 0) logits[gw] = acc;
}

__global__ void attn_softmax(const float* __restrict__ logits, float* __restrict__ att)
{
    int b = blockIdx.x, t = threadIdx.x;
    __shared__ float red[256];
    float v = (t < LL) ? logits[t * BB + b] : -1e30f;
    red[t] = v;
    __syncthreads();
    for (int s = 128; s > 0; s >>= 1) {
        if (t < s) red[t] = fmaxf(red[t], red[t + s]);
        __syncthreads();
    }
    float mx = red[0];
    __syncthreads();
    float e = (t < LL) ? expf(v - mx) : 0.f;
    red[t] = e;
    __syncthreads();
    for (int s = 128; s > 0; s >>= 1) {
        if (t < s) red[t] += red[t + s];
        __syncthreads();
    }
    float inv = 1.f / red[0];
    if (t < LL) att[t * BB + b] = e * inv;
}

// ---------------- host ----------------
extern "C" void kernel_launch(void* const* d_in, const int* in_sizes, int n_in,
                              void* d_out, int out_size)
{
    const float* session  = (const float*)d_in[0];
    const float* target   = (const float*)d_in[1];
    const float* w        = (const float*)d_in[2];
    const float* wih      = (const float*)d_in[3];
    const float* whh      = (const float*)d_in[4];
    const float* bih      = (const float*)d_in[5];
    const float* bhh      = (const float*)d_in[6];
    const float* reset_w  = (const float*)d_in[7];
    const float* reset_b  = (const float*)d_in[8];
    const float* update_w = (const float*)d_in[9];
    const float* update_b = (const float*)d_in[10];
    const float* hhat_w   = (const float*)d_in[11];
    const float* hhat_b   = (const float*)d_in[12];
    float* out = (float*)d_out;

    float *xproj, *sseq, *rx, *ux, *nx, *u, *logits, *att, *ue, *hf, *zero;
    u32 *Psess, *Ptar, *Psseq, *Phr, *Pp;
    u32 *Fwih, *Fwhh, *Fw, *Frh, *Fuh, *Fhh, *Frx, *Fux, *Fhx;

    cudaGetSymbolAddress((void**)&xproj,  g_xproj);
    cudaGetSymbolAddress((void**)&sseq,   g_sseq);
    cudaGetSymbolAddress((void**)&rx,     g_rx);
    cudaGetSymbolAddress((void**)&ux,     g_ux);
    cudaGetSymbolAddress((void**)&nx,     g_nx);
    cudaGetSymbolAddress((void**)&u,      g_u);
    cudaGetSymbolAddress((void**)&logits, g_logits);
    cudaGetSymbolAddress((void**)&att,    g_att);
    cudaGetSymbolAddress((void**)&ue,     g_ue);
    cudaGetSymbolAddress((void**)&hf,     g_hf);
    cudaGetSymbolAddress((void**)&zero,   g_zero);
    cudaGetSymbolAddress((void**)&Psess,  g_Psess);
    cudaGetSymbolAddress((void**)&Ptar,   g_Ptar);
    cudaGetSymbolAddress((void**)&Psseq,  g_Psseq);
    cudaGetSymbolAddress((void**)&Phr,    g_Phr);
    cudaGetSymbolAddress((void**)&Pp,     g_Pp);
    cudaGetSymbolAddress((void**)&Fwih,   g_Fwih);
    cudaGetSymbolAddress((void**)&Fwhh,   g_Fwhh);
    cudaGetSymbolAddress((void**)&Fw,     g_Fw);
    cudaGetSymbolAddress((void**)&Frh,    g_Frh);
    cudaGetSymbolAddress((void**)&Fuh,    g_Fuh);
    cudaGetSymbolAddress((void**)&Fhh,    g_Fhh);
    cudaGetSymbolAddress((void**)&Frx,    g_Frx);
    cudaGetSymbolAddress((void**)&Fux,    g_Fux);
    cudaGetSymbolAddress((void**)&Fhx,    g_Fhx);

    // opt-in large dynamic smem for the persistent recurrence kernels
    cudaFuncSetAttribute(gru3,   cudaFuncAttributeMaxDynamicSharedMemorySize, DSMEM_BYTES);
    cudaFuncSetAttribute(augru3, cudaFuncAttributeMaxDynamicSharedMemorySize, DSMEM_BYTES);

    // launch 1: pack session + zero buffer
    pack_zero_kernel<<<(BB * LL * DD / 4 + 255) / 256, 256>>>(
        session, Psess, BB * LL * DD / 4, zero, BB * DD / 4);
    // launch 2: both GRU weight fragment sets
    wfrag2_kernel<<<(2 * 1536 * DD + 255) / 256, 256>>>(wih, whh, Fwih, Fwhh, 1536 * DD);
    // launch 3: x_proj
    {
        dim3 g(BB * LL / 128, 3 * DD / 64);
        mm_big<<<g, 256>>>(Psess, Fwih, bih, xproj, 3 * DD);
    }
    // launch 4: persistent GRU  <- ncu capture slot
    gru3<<<128, 512, DSMEM_BYTES>>>(zero, (const u32*)zero, Fwhh, bhh, xproj, sseq, Psseq);

    // remaining prep
    pack_kernel<<<(BB * DD / 4 + 255) / 256, 256>>>(target, Ptar, BB * DD / 4);
    wfrag_kernel<<<(DD * DD + 255) / 256, 256>>>(w,        DD,     0,  Fw,  DD * DD);
    wfrag_kernel<<<(DD * DD + 255) / 256, 256>>>(reset_w,  2 * DD, 0,  Frh, DD * DD);
    wfrag_kernel<<<(DD * DD + 255) / 256, 256>>>(update_w, 2 * DD, 0,  Fuh, DD * DD);
    wfrag_kernel<<<(DD * DD + 255) / 256, 256>>>(hhat_w,   2 * DD, 0,  Fhh, DD * DD);
    wfrag_kernel<<<(DD * DD + 255) / 256, 256>>>(reset_w,  2 * DD, DD, Frx, DD * DD);
    wfrag_kernel<<<(DD * DD + 255) / 256, 256>>>(update_w, 2 * DD, DD, Fux, DD * DD);
    wfrag_kernel<<<(DD * DD + 255) / 256, 256>>>(hhat_w,   2 * DD, DD, Fhx, DD * DD);

    // u = target @ w^T
    {
        dim3 g(BB / 128, DD / 64);
        mm_big<<<g, 256>>>(Ptar, Fw, nullptr, u, DD);
    }
    // AUGRU x-projections (biases folded)
    {
        dim3 g(BB * LL / 128, DD / 64);
        mm_big<<<g, 256>>>(Psseq, Frx, reset_b,  rx, DD);
        mm_big<<<g, 256>>>(Psseq, Fux, update_b, ux, DD);
        mm_big<<<g, 256>>>(Psseq, Fhx, hhat_b,   nx, DD);
    }
    // attention
    attn_logits<<<LL * BB / 8, 256>>>(sseq, u, logits);
    attn_softmax<<<BB, 256>>>(logits, att);

    // persistent AUGRU; init h = sseq[L-1]
    augru3<<<128, 512, DSMEM_BYTES>>>(sseq + (size_t)(LL - 1) * BBDD,
                                      Psseq + (size_t)(LL - 1) * BBDD,
                                      Frh, Fuh, Fhh,
                                      rx, ux, nx, att,
                                      hf, Pp, Phr, ue, out);
}

// round 16
// speedup vs baseline: 1.4338x; 1.4338x over previous
#include <cuda_runtime.h>
#include <cuda_bf16.h>
#include <math.h>
#include <stdint.h>

#define BB 256
#define LL 200
#define DD 512
#define BBDD (BB * DD)
typedef uint32_t u32;

// ---------------- fp32 scratch ----------------
__device__ float g_xproj[(size_t)BB * LL * 3 * DD];   // [B,L,3D] (+bih)
__device__ float g_sseq [(size_t)LL * BB * DD];       // [L,B,D]
__device__ float g_rx   [(size_t)LL * BB * DD];
__device__ float g_ux   [(size_t)LL * BB * DD];
__device__ float g_nx   [(size_t)LL * BB * DD];
__device__ float g_u    [BB * DD];
__device__ float g_logits[LL * BB];
__device__ float g_att   [LL * BB];
__device__ float g_ue    [BB * DD];
__device__ float g_hf    [2 * BB * DD];
__device__ float g_zero  [BB * DD];                   // fp32 zeros == packed zeros

// ---------------- packed (bf16-pair) activations ----------------
__device__ u32 g_Psess[(size_t)BB * LL * DD];
__device__ u32 g_Ptar [BB * DD];
__device__ u32 g_Psseq[(size_t)LL * BB * DD];
__device__ u32 g_Phr  [BB * DD];
__device__ u32 g_Pp   [2 * BB * DD];

// ---------------- weight fragments (B-operand order) ----------------
__device__ u32 g_Fwih[1536 * DD];
__device__ u32 g_Fwhh[1536 * DD];
__device__ u32 g_Fw  [DD * DD];
__device__ u32 g_Frh [DD * DD];
__device__ u32 g_Fuh [DD * DD];
__device__ u32 g_Fhh [DD * DD];
__device__ u32 g_Frx [DD * DD];
__device__ u32 g_Fux [DD * DD];
__device__ u32 g_Fhx [DD * DD];

// per-row-group barriers (8 groups of 16 blocks, counters padded)
__device__ unsigned int          g_gcnt[16 * 32];
__device__ volatile unsigned int g_ggen[16 * 32];

__device__ __forceinline__ float sigf(float x) { return 1.0f / (1.0f + __expf(-x)); }

__device__ __forceinline__ u32 packbf(float x) {
    __nv_bfloat16 hi = __float2bfloat16(x);
    float hf = __bfloat162float(hi);
    __nv_bfloat16 lo = __float2bfloat16(x - hf);
    return (u32)__bfloat16_as_ushort(hi) | ((u32)__bfloat16_as_ushort(lo) << 16);
}

__device__ __forceinline__ void pf2(const void* p) {
    asm volatile("prefetch.global.L2 [%0];" :: "l"(p));
}

// 16-block barrier over one row group
__device__ __forceinline__ void group_barrier(int mi) {
    __syncthreads();
    if (threadIdx.x == 0) {
        __threadfence();
        unsigned int gen = g_ggen[mi * 32];
        unsigned int old = atomicAdd(&g_gcnt[mi * 32], 1u);
        if (old == 15u) {
            atomicExch(&g_gcnt[mi * 32], 0u);
            __threadfence();
            atomicAdd((unsigned int*)&g_ggen[mi * 32], 1u);
        } else {
            while (g_ggen[mi * 32] == gen) { }
        }
        __threadfence();
    }
    __syncthreads();
}

__device__ __forceinline__ void mma16(float* d, const u32* a, u32 b0, u32 b1) {
    asm volatile(
        "mma.sync.aligned.m16n8k16.row.col.f32.bf16.bf16.f32 "
        "{%0,%1,%2,%3},{%4,%5,%6,%7},{%8,%9},{%0,%1,%2,%3};"
        : "+f"(d[0]), "+f"(d[1]), "+f"(d[2]), "+f"(d[3])
        : "r"(a[0]), "r"(a[1]), "r"(a[2]), "r"(a[3]), "r"(b0), "r"(b1));
}

// ==================================================================
// 256-thread 128x64 core (unchanged — proven) for the big GEMMs
// ==================================================================
struct MMSmem { u32 A[2][16][136]; };

__device__ __forceinline__ void mm_core(
    MMSmem* sm, const u32* __restrict__ Ap,
    const u32* __restrict__ F, int gnt0,
    float acc[2][4][4])
{
    const int tid  = threadIdx.x;
    const int lane = tid & 31;
    const int gq = lane >> 2, tq = lane & 3;
    const int w  = tid >> 5;
    const int wm = w >> 1, wn = w & 1;
    const int r  = tid >> 1, h = tid & 1;

    const u32* arow = Ap + (size_t)r * DD + h * 8;

    uint4 bv[4], nbv[4], na0, na1;

    uint4 va0 = *(const uint4*)(arow + 0);
    uint4 va1 = *(const uint4*)(arow + 4);
    #pragma unroll
    for (int nt = 0; nt < 4; nt++) {
        int gnt = gnt0 + wn * 4 + nt;
        bv[nt] = *(const uint4*)(F + (((size_t)gnt * 32 + 0) * 32 + lane) * 4);
    }
    {
        u32 e0[4] = {va0.x, va0.y, va0.z, va0.w};
        u32 e1[4] = {va1.x, va1.y, va1.z, va1.w};
        #pragma unroll
        for (int j = 0; j < 4; j++) {
            int jj = (j + 2 * h) & 3;
            sm->A[0][h * 8 + 0 + jj][r] = e0[jj];
            sm->A[0][h * 8 + 4 + jj][r] = e1[jj];
        }
    }
    __syncthreads();

    #pragma unroll 1
    for (int s2 = 0; s2 < 32; s2++) {
        const int buf = s2 & 1;
        if (s2 < 31) {
            const u32* ar = arow + (s2 + 1) * 16;
            na0 = *(const uint4*)(ar);
            na1 = *(const uint4*)(ar + 4);
            #pragma unroll
            for (int nt = 0; nt < 4; nt++) {
                int gnt = gnt0 + wn * 4 + nt;
                nbv[nt] = *(const uint4*)(F + (((size_t)gnt * 32 + (s2 + 1)) * 32 + lane) * 4);
            }
        }
        #pragma unroll
        for (int sl = 0; sl < 2; sl++) {
            u32 a[2][4], as[2][4];
            #pragma unroll
            for (int mt = 0; mt < 2; mt++) {
                int rb = wm * 32 + mt * 16 + gq;
                a[mt][0] = sm->A[buf][sl * 8 + tq][rb];
                a[mt][1] = sm->A[buf][sl * 8 + tq][rb + 8];
                a[mt][2] = sm->A[buf][sl * 8 + tq + 4][rb];
                a[mt][3] = sm->A[buf][sl * 8 + tq + 4][rb + 8];
                #pragma unroll
                for (int q = 0; q < 4; q++)
                    as[mt][q] = __funnelshift_l(a[mt][q], a[mt][q], 16);
            }
            #pragma unroll
            for (int nt = 0; nt < 4; nt++) {
                u32 b0 = sl ? bv[nt].z : bv[nt].x;
                u32 b1 = sl ? bv[nt].w : bv[nt].y;
                #pragma unroll
                for (int mt = 0; mt < 2; mt++) {
                    mma16(acc[mt][nt], a[mt],  b0, b1);
                    mma16(acc[mt][nt], as[mt], b0, b1);
                }
            }
        }
        if (s2 < 31) {
            u32 e0[4] = {na0.x, na0.y, na0.z, na0.w};
            u32 e1[4] = {na1.x, na1.y, na1.z, na1.w};
            #pragma unroll
            for (int j = 0; j < 4; j++) {
                int jj = (j + 2 * h) & 3;
                sm->A[buf ^ 1][h * 8 + 0 + jj][r] = e0[jj];
                sm->A[buf ^ 1][h * 8 + 4 + jj][r] = e1[jj];
            }
            #pragma unroll
            for (int nt = 0; nt < 4; nt++) bv[nt] = nbv[nt];
        }
        __syncthreads();
    }
}

__global__ __launch_bounds__(256) void mm_big(
    const u32* __restrict__ Ap,
    const u32* __restrict__ F,
    const float* __restrict__ bias,
    float* __restrict__ C, int ldc)
{
    __shared__ MMSmem sm;
    const int bm = blockIdx.x * 128, bn = blockIdx.y * 64;
    float acc[2][4][4];
    #pragma unroll
    for (int i = 0; i < 2; i++)
        #pragma unroll
        for (int j = 0; j < 4; j++)
            #pragma unroll
            for (int e = 0; e < 4; e++) acc[i][j][e] = 0.f;
    mm_core(&sm, Ap + (size_t)bm * DD, F, bn >> 3, acc);

    const int lane = threadIdx.x & 31;
    const int gq = lane >> 2, tq = lane & 3;
    const int w = threadIdx.x >> 5;
    const int wm = w >> 1, wn = w & 1;
    #pragma unroll
    for (int mt = 0; mt < 2; mt++)
        #pragma unroll
        for (int nt = 0; nt < 4; nt++) {
            int row = bm + wm * 32 + mt * 16 + gq;
            int col = bn + wn * 32 + nt * 8 + 2 * tq;
            float b0 = bias ? bias[col] : 0.f;
            float b1 = bias ? bias[col + 1] : 0.f;
            *(float2*)(C + (size_t)row * ldc + col) =
                make_float2(acc[mt][nt][0] + b0, acc[mt][nt][1] + b1);
            *(float2*)(C + (size_t)(row + 8) * ldc + col) =
                make_float2(acc[mt][nt][2] + b0, acc[mt][nt][3] + b1);
        }
}

// ==================================================================
// Row-group recurrence core: 32 rows x 32 h-cols x NG gates, 512 thr
// Warps: 4 k-quarters x 2 m-tiles x 2 n-warps.
// SINGLE-SHOT A tile [kq][row32][128+4] (dynamic smem, 66 KB; Red overlays)
// ==================================================================
#define ASM_WORDS (4 * 32 * 132)
#define RDSM_BYTES (ASM_WORDS * 4)     // 67,584 B (>= 384*25*4 = 38,400)

template<int NG>
__device__ __forceinline__ void rec_coreG(
    u32* Asm, float* Red, const u32* __restrict__ Ap,   // 32 rows, stride DD
    const u32* const* Fp, const int* gb,
    float acc[NG][2][4])
{
    const int tid  = threadIdx.x;
    const int lane = tid & 31;
    const int gq = lane >> 2, tq = lane & 3;
    const int w  = tid >> 5;
    const int wk = w >> 2;              // k-quarter 0..3
    const int wm = (w >> 1) & 1;        // m-tile 0..1
    const int wn = w & 1;               // n-warp 0..1

    // one-shot A load: 512 threads x 8 uint4
    {
        const int lkq = tid >> 7;
        const int lr  = (tid >> 2) & 31;
        const int lsg = tid & 3;
        const u32* arow = Ap + (size_t)lr * DD + lkq * 128 + lsg * 4;
        u32* dst = Asm + (lkq * 32 + lr) * 132 + lsg * 4;
        #pragma unroll
        for (int s = 0; s < 8; s++)
            *(uint4*)(dst + s * 16) = *(const uint4*)(arow + s * 16);
    }

    uint4 bv[NG][2], nbv[NG][2];
    #pragma unroll
    for (int g = 0; g < NG; g++)
        #pragma unroll
        for (int nt = 0; nt < 2; nt++)
            bv[g][nt] = *(const uint4*)(Fp[g] +
                (((size_t)(gb[g] + wn * 2 + nt) * 32 + wk * 8) * 32 + lane) * 4);

    __syncthreads();

    const u32* arow0 = Asm + (wk * 32 + wm * 16 + gq) * 132;
    const u32* arow1 = Asm + (wk * 32 + wm * 16 + gq + 8) * 132;

    #pragma unroll 1
    for (int s2 = 0; s2 < 8; s2++) {
        if (s2 < 7) {
            #pragma unroll
            for (int g = 0; g < NG; g++)
                #pragma unroll
                for (int nt = 0; nt < 2; nt++)
                    nbv[g][nt] = *(const uint4*)(Fp[g] +
                        (((size_t)(gb[g] + wn * 2 + nt) * 32 + wk * 8 + s2 + 1) * 32 + lane) * 4);
        }
        #pragma unroll
        for (int sl = 0; sl < 2; sl++) {
            const int kb = s2 * 16 + sl * 8;
            u32 a[4], as[4];
            a[0] = arow0[kb + tq];
            a[1] = arow1[kb + tq];
            a[2] = arow0[kb + tq + 4];
            a[3] = arow1[kb + tq + 4];
            #pragma unroll
            for (int q = 0; q < 4; q++) as[q] = __funnelshift_l(a[q], a[q], 16);
            #pragma unroll
            for (int g = 0; g < NG; g++)
                #pragma unroll
                for (int nt = 0; nt < 2; nt++) {
                    u32 b0 = sl ? bv[g][nt].z : bv[g][nt].x;
                    u32 b1 = sl ? bv[g][nt].w : bv[g][nt].y;
                    mma16(acc[g][nt], a,  b0, b1);
                    mma16(acc[g][nt], as, b0, b1);
                }
        }
        if (s2 < 7) {
            #pragma unroll
            for (int g = 0; g < NG; g++) {
                bv[g][0] = nbv[g][0];
                bv[g][1] = nbv[g][1];
            }
        }
    }

    __syncthreads();   // A dead; Red overlays

    // reduce wk=1..3 partials into wk=0 (stride 25: conflict-free)
    const int stride = NG * 8 + 1;
    if (wk) {
        int base = (tid - 128) * stride;
        #pragma unroll
        for (int g = 0; g < NG; g++)
            #pragma unroll
            for (int nt = 0; nt < 2; nt++)
                #pragma unroll
                for (int e = 0; e < 4; e++)
                    Red[base + (g * 2 + nt) * 4 + e] = acc[g][nt][e];
    }
    __syncthreads();
    if (!wk) {
        #pragma unroll
        for (int k = 0; k < 3; k++) {
            int base = (k * 128 + tid) * stride;
            #pragma unroll
            for (int g = 0; g < NG; g++)
                #pragma unroll
                for (int nt = 0; nt < 2; nt++)
                    #pragma unroll
                    for (int e = 0; e < 4; e++)
                        acc[g][nt][e] += Red[base + (g * 2 + nt) * 4 + e];
        }
    }
    __syncthreads();
}

// ---------------- persistent GRU: 8 row-groups x 16 col-blocks ----------------
__global__ __launch_bounds__(512) void gru2G(
    const float* __restrict__ zero, const u32* __restrict__ Pzero,
    const u32* __restrict__ Fwhh, const float* __restrict__ bhh,
    const float* __restrict__ xproj,
    float* __restrict__ sseq, u32* __restrict__ Psseq)
{
    extern __shared__ u32 dynsm[];
    u32* Asm = dynsm;
    float* Red = (float*)dynsm;

    const int blk = blockIdx.x;
    const int mi = blk >> 4, di = blk & 15;
    const int bm = mi * 32;
    const int tid = threadIdx.x;
    const int lane = tid & 31;
    const int gq = lane >> 2, tq = lane & 3;
    const int w = tid >> 5;
    const int wm = (w >> 1) & 1, wn = w & 1;

    const u32* Fp[3] = {Fwhh, Fwhh, Fwhh};
    int gb[3] = {di * 4, 64 + di * 4, 128 + di * 4};

    float bh[3][2][2];
    #pragma unroll
    for (int g = 0; g < 3; g++)
        #pragma unroll
        for (int nt = 0; nt < 2; nt++) {
            int col = di * 32 + wn * 16 + nt * 8 + 2 * tq;
            bh[g][nt][0] = bhh[g * 512 + col];
            bh[g][nt][1] = bhh[g * 512 + col + 1];
        }

    for (int l = 0; l < LL; l++) {
        const u32* Ap = (l ? Psseq + (size_t)(l - 1) * BBDD : Pzero) + (size_t)bm * DD;
        const float* hprev = l ? sseq + (size_t)(l - 1) * BBDD : zero;

        if (tid < 128) {   // prefetch epilogue lines (overlaps GEMM)
            int colp = di * 32 + wn * 16;
            #pragma unroll
            for (int half = 0; half < 2; half++) {
                int row = bm + wm * 16 + gq + half * 8;
                const float* xb = xproj + ((size_t)row * LL + l) * 1536 + colp;
                pf2(xb); pf2(xb + 512); pf2(xb + 1024);
                pf2(hprev + (size_t)row * DD + colp);
            }
        }

        float acc[3][2][4];
        #pragma unroll
        for (int g = 0; g < 3; g++)
            #pragma unroll
            for (int nt = 0; nt < 2; nt++)
                #pragma unroll
                for (int e = 0; e < 4; e++) acc[g][nt][e] = 0.f;

        rec_coreG<3>(Asm, Red, Ap, Fp, gb, acc);

        if (tid < 128) {
            float* sl_ = sseq + (size_t)l * BBDD;
            u32* pl = Psseq + (size_t)l * BBDD;

            #pragma unroll
            for (int nt = 0; nt < 2; nt++) {
                int col = di * 32 + wn * 16 + nt * 8 + 2 * tq;
                #pragma unroll
                for (int half = 0; half < 2; half++) {
                    int row = bm + wm * 16 + gq + half * 8;
                    const float* xb = xproj + ((size_t)row * LL + l) * 1536;
                    size_t ix = (size_t)row * DD + col;
                    #pragma unroll
                    for (int c = 0; c < 2; c++) {
                        int e = half * 2 + c;
                        float rr = sigf(xb[col + c] + acc[0][nt][e] + bh[0][nt][c]);
                        float zz = sigf(xb[512 + col + c] + acc[1][nt][e] + bh[1][nt][c]);
                        float nn = tanhf(xb[1024 + col + c] + rr * (acc[2][nt][e] + bh[2][nt][c]));
                        float h0 = hprev[ix + c];
                        float hn = nn + zz * (h0 - nn);
                        sl_[ix + c] = hn;
                        pl[ix + c] = packbf(hn);
                    }
                }
            }
        }

        group_barrier(mi);
    }
}

// ---------------- persistent AUGRU: same grouping ----------------
__global__ __launch_bounds__(512) void augru2G(
    const float* __restrict__ hlast, const u32* __restrict__ Pinit,
    const u32* __restrict__ Frh, const u32* __restrict__ Fuh, const u32* __restrict__ Fhh,
    const float* __restrict__ rx, const float* __restrict__ ux, const float* __restrict__ nx,
    const float* __restrict__ att,
    float* __restrict__ hf, u32* __restrict__ Pp,
    u32* __restrict__ Phr, float* __restrict__ ue,
    float* __restrict__ out)
{
    extern __shared__ u32 dynsm[];
    u32* Asm = dynsm;
    float* Red = (float*)dynsm;

    const int blk = blockIdx.x;
    const int mi = blk >> 4, di = blk & 15;
    const int bm = mi * 32;
    const int tid = threadIdx.x;
    const int lane = tid & 31;
    const int gq = lane >> 2, tq = lane & 3;
    const int w = tid >> 5;
    const int wm = (w >> 1) & 1, wn = w & 1;

    for (int l = 0; l < LL; l++) {
        const float* hc = l ? hf + (size_t)(l & 1) * BBDD : hlast;
        const u32* Pc = l ? Pp + (size_t)(l & 1) * BBDD : Pinit;

        {   // phase A: r and u_eff
            if (tid < 128) {
                int colp = di * 32 + wn * 16;
                const float* rxl = rx + (size_t)l * BBDD;
                const float* uxl = ux + (size_t)l * BBDD;
                const float* nxl = nx + (size_t)l * BBDD;
                #pragma unroll
                for (int half = 0; half < 2; half++) {
                    int row = bm + wm * 16 + gq + half * 8;
                    size_t ixp = (size_t)row * DD + colp;
                    pf2(rxl + ixp); pf2(uxl + ixp); pf2(nxl + ixp);
                    pf2(hc + ixp);
                }
                pf2(att + (size_t)l * BB + bm);
            }

            const u32* Fp[2] = {Frh, Fuh};
            int gb[2] = {di * 4, di * 4};
            float acc[2][2][4];
            #pragma unroll
            for (int g = 0; g < 2; g++)
                #pragma unroll
                for (int nt = 0; nt < 2; nt++)
                    #pragma unroll
                    for (int e = 0; e < 4; e++) acc[g][nt][e] = 0.f;

            rec_coreG<2>(Asm, Red, Pc + (size_t)bm * DD, Fp, gb, acc);

            if (tid < 128) {
                const float* rxl = rx + (size_t)l * BBDD;
                const float* uxl = ux + (size_t)l * BBDD;
                #pragma unroll
                for (int nt = 0; nt < 2; nt++) {
                    int col = di * 32 + wn * 16 + nt * 8 + 2 * tq;
                    #pragma unroll
                    for (int half = 0; half < 2; half++) {
                        int row = bm + wm * 16 + gq + half * 8;
                        size_t ix = (size_t)row * DD + col;
                        float a = att[(size_t)l * BB + row];
                        #pragma unroll
                        for (int c = 0; c < 2; c++) {
                            int e = half * 2 + c;
                            float vr = acc[0][nt][e] + rxl[ix + c];
                            float vu = acc[1][nt][e] + uxl[ix + c];
                            Phr[ix + c] = packbf(hc[ix + c] * sigf(vr));
                            ue[ix + c]  = a * sigf(vu);
                        }
                    }
                }
            }
        }

        group_barrier(mi);

        {   // phase B: hhat + output update
            const u32* Fp[1] = {Fhh};
            int gb[1] = {di * 4};
            float acc[1][2][4];
            #pragma unroll
            for (int nt = 0; nt < 2; nt++)
                #pragma unroll
                for (int e = 0; e < 4; e++) acc[0][nt][e] = 0.f;

            rec_coreG<1>(Asm, Red, Phr + (size_t)bm * DD, Fp, gb, acc);

            if (tid < 128) {
                float* ho = (l == LL - 1) ? out : hf + (size_t)((l + 1) & 1) * BBDD;
                u32* Pn = Pp + (size_t)((l + 1) & 1) * BBDD;
                const float* nxl = nx + (size_t)l * BBDD;
                #pragma unroll
                for (int nt = 0; nt < 2; nt++) {
                    int col = di * 32 + wn * 16 + nt * 8 + 2 * tq;
                    #pragma unroll
                    for (int half = 0; half < 2; half++) {
                        int row = bm + wm * 16 + gq + half * 8;
                        size_t ix = (size_t)row * DD + col;
                        #pragma unroll
                        for (int c = 0; c < 2; c++) {
                            int e = half * 2 + c;
                            float hh = tanhf(acc[0][nt][e] + nxl[ix + c]);
                            float h0 = hc[ix + c];
                            float u0 = ue[ix + c];
                            float hn = h0 + u0 * (hh - h0);
                            ho[ix + c] = hn;
                            Pn[ix + c] = packbf(hn);
                        }
                    }
                }
            }
        }

        group_barrier(mi);
    }
}

// ---------------- conversion kernels ----------------
__global__ void pack_zero_kernel(const float* __restrict__ x, u32* __restrict__ p, int n4,
                                 float* __restrict__ z, int zn4)
{
    int i = blockIdx.x * 256 + threadIdx.x;
    if (i < n4) {
        float4 v = ((const float4*)x)[i];
        uint4 o;
        o.x = packbf(v.x); o.y = packbf(v.y); o.z = packbf(v.z); o.w = packbf(v.w);
        ((uint4*)p)[i] = o;
    }
    if (i < zn4) ((float4*)z)[i] = make_float4(0.f, 0.f, 0.f, 0.f);
}

__global__ void pack_kernel(const float* __restrict__ x, u32* __restrict__ p, int n4)
{
    int i = blockIdx.x * 256 + threadIdx.x;
    if (i < n4) {
        float4 v = ((const float4*)x)[i];
        uint4 o;
        o.x = packbf(v.x); o.y = packbf(v.y); o.z = packbf(v.z); o.w = packbf(v.w);
        ((uint4*)p)[i] = o;
    }
}

__device__ __forceinline__ void wfrag_one(const float* W, int ldw, int woff,
                                          u32* F, int idx)
{
    int j = idx & 3, lane = (idx >> 2) & 31, s2 = (idx >> 7) & 31, gnt = idx >> 12;
    int g = lane >> 2, t = lane & 3;
    int sl = s2 * 2 + (j >> 1), b = j & 1;
    int ok = sl * 8 + t + 4 * b;
    int n = gnt * 8 + g;
    F[idx] = packbf(W[(size_t)n * ldw + woff + ok]);
}

__global__ void wfrag2_kernel(const float* __restrict__ W1, const float* __restrict__ W2,
                              u32* __restrict__ F1, u32* __restrict__ F2, int total)
{
    int idx0 = blockIdx.x * 256 + threadIdx.x;
    if (idx0 < total)               wfrag_one(W1, DD, 0, F1, idx0);
    else if (idx0 < 2 * total)      wfrag_one(W2, DD, 0, F2, idx0 - total);
}

__global__ void wfrag_kernel(const float* __restrict__ W, int ldw, int woff,
                             u32* __restrict__ F, int total)
{
    int idx = blockIdx.x * 256 + threadIdx.x;
    if (idx < total) wfrag_one(W, ldw, woff, F, idx);
}

// ---------------- attention ----------------
__global__ void attn_logits(const float* __restrict__ s, const float* __restrict__ u,
                            float* __restrict__ logits)
{
    int gw = (blockIdx.x * blockDim.x + threadIdx.x) >> 5;
    int lane = threadIdx.x & 31;
    int b = gw & (BB - 1);
    const float4* sr = (const float4*)(s + (size_t)gw * DD);
    const float4* ur = (const float4*)(u + (size_t)b * DD);
    float acc = 0.f;
    #pragma unroll
    for (int k = lane; k < DD / 4; k += 32) {
        float4 a = sr[k], c = ur[k];
        acc += a.x * c.x + a.y * c.y + a.z * c.z + a.w * c.w;
    }
    #pragma unroll
    for (int o = 16; o > 0; o >>= 1) acc += __shfl_xor_sync(0xffffffffu, acc, o);
    if (lane == 0) logits[gw] = acc;
}

__global__ void attn_softmax(const float* __restrict__ logits, float* __restrict__ att)
{
    int b = blockIdx.x, t = threadIdx.x;
    __shared__ float red[256];
    float v = (t < LL) ? logits[t * BB + b] : -1e30f;
    red[t] = v;
    __syncthreads();
    for (int s = 128; s > 0; s >>= 1) {
        if (t < s) red[t] = fmaxf(red[t], red[t + s]);
        __syncthreads();
    }
    float mx = red[0];
    __syncthreads();
    float e = (t < LL) ? expf(v - mx) : 0.f;
    red[t] = e;
    __syncthreads();
    for (int s = 128; s > 0; s >>= 1) {
        if (t < s) red[t] += red[t + s];
        __syncthreads();
    }
    float inv = 1.f / red[0];
    if (t < LL) att[t * BB + b] = e * inv;
}

// ---------------- host ----------------
extern "C" void kernel_launch(void* const* d_in, const int* in_sizes, int n_in,
                              void* d_out, int out_size)
{
    const float* session  = (const float*)d_in[0];
    const float* target   = (const float*)d_in[1];
    const float* w        = (const float*)d_in[2];
    const float* wih      = (const float*)d_in[3];
    const float* whh      = (const float*)d_in[4];
    const float* bih      = (const float*)d_in[5];
    const float* bhh      = (const float*)d_in[6];
    const float* reset_w  = (const float*)d_in[7];
    const float* reset_b  = (const float*)d_in[8];
    const float* update_w = (const float*)d_in[9];
    const float* update_b = (const float*)d_in[10];
    const float* hhat_w   = (const float*)d_in[11];
    const float* hhat_b   = (const float*)d_in[12];
    float* out = (float*)d_out;

    float *xproj, *sseq, *rx, *ux, *nx, *u, *logits, *att, *ue, *hf, *zero;
    u32 *Psess, *Ptar, *Psseq, *Phr, *Pp;
    u32 *Fwih, *Fwhh, *Fw, *Frh, *Fuh, *Fhh, *Frx, *Fux, *Fhx;

    cudaGetSymbolAddress((void**)&xproj,  g_xproj);
    cudaGetSymbolAddress((void**)&sseq,   g_sseq);
    cudaGetSymbolAddress((void**)&rx,     g_rx);
    cudaGetSymbolAddress((void**)&ux,     g_ux);
    cudaGetSymbolAddress((void**)&nx,     g_nx);
    cudaGetSymbolAddress((void**)&u,      g_u);
    cudaGetSymbolAddress((void**)&logits, g_logits);
    cudaGetSymbolAddress((void**)&att,    g_att);
    cudaGetSymbolAddress((void**)&ue,     g_ue);
    cudaGetSymbolAddress((void**)&hf,     g_hf);
    cudaGetSymbolAddress((void**)&zero,   g_zero);
    cudaGetSymbolAddress((void**)&Psess,  g_Psess);
    cudaGetSymbolAddress((void**)&Ptar,   g_Ptar);
    cudaGetSymbolAddress((void**)&Psseq,  g_Psseq);
    cudaGetSymbolAddress((void**)&Phr,    g_Phr);
    cudaGetSymbolAddress((void**)&Pp,     g_Pp);
    cudaGetSymbolAddress((void**)&Fwih,   g_Fwih);
    cudaGetSymbolAddress((void**)&Fwhh,   g_Fwhh);
    cudaGetSymbolAddress((void**)&Fw,     g_Fw);
    cudaGetSymbolAddress((void**)&Frh,    g_Frh);
    cudaGetSymbolAddress((void**)&Fuh,    g_Fuh);
    cudaGetSymbolAddress((void**)&Fhh,    g_Fhh);
    cudaGetSymbolAddress((void**)&Frx,    g_Frx);
    cudaGetSymbolAddress((void**)&Fux,    g_Fux);
    cudaGetSymbolAddress((void**)&Fhx,    g_Fhx);

    cudaFuncSetAttribute(gru2G,   cudaFuncAttributeMaxDynamicSharedMemorySize, RDSM_BYTES);
    cudaFuncSetAttribute(augru2G, cudaFuncAttributeMaxDynamicSharedMemorySize, RDSM_BYTES);

    // launch 1: pack session + zero buffer
    pack_zero_kernel<<<(BB * LL * DD / 4 + 255) / 256, 256>>>(
        session, Psess, BB * LL * DD / 4, zero, BB * DD / 4);
    // launch 2: both GRU weight fragment sets
    wfrag2_kernel<<<(2 * 1536 * DD + 255) / 256, 256>>>(wih, whh, Fwih, Fwhh, 1536 * DD);
    // launch 3: x_proj
    {
        dim3 g(BB * LL / 128, 3 * DD / 64);
        mm_big<<<g, 256>>>(Psess, Fwih, bih, xproj, 3 * DD);
    }
    // launch 4: persistent GRU  <- ncu capture slot
    gru2G<<<128, 512, RDSM_BYTES>>>(zero, (const u32*)zero, Fwhh, bhh, xproj, sseq, Psseq);

    // remaining prep
    pack_kernel<<<(BB * DD / 4 + 255) / 256, 256>>>(target, Ptar, BB * DD / 4);
    wfrag_kernel<<<(DD * DD + 255) / 256, 256>>>(w,        DD,     0,  Fw,  DD * DD);
    wfrag_kernel<<<(DD * DD + 255) / 256, 256>>>(reset_w,  2 * DD, 0,  Frh, DD * DD);
    wfrag_kernel<<<(DD * DD + 255) / 256, 256>>>(update_w, 2 * DD, 0,  Fuh, DD * DD);
    wfrag_kernel<<<(DD * DD + 255) / 256, 256>>>(hhat_w,   2 * DD, 0,  Fhh, DD * DD);
    wfrag_kernel<<<(DD * DD + 255) / 256, 256>>>(reset_w,  2 * DD, DD, Frx, DD * DD);
    wfrag_kernel<<<(DD * DD + 255) / 256, 256>>>(update_w, 2 * DD, DD, Fux, DD * DD);
    wfrag_kernel<<<(DD * DD + 255) / 256, 256>>>(hhat_w,   2 * DD, DD, Fhx, DD * DD);

    // u = target @ w^T
    {
        dim3 g(BB / 128, DD / 64);
        mm_big<<<g, 256>>>(Ptar, Fw, nullptr, u, DD);
    }
    // AUGRU x-projections (biases folded)
    {
        dim3 g(BB * LL / 128, DD / 64);
        mm_big<<<g, 256>>>(Psseq, Frx, reset_b,  rx, DD);
        mm_big<<<g, 256>>>(Psseq, Fux, update_b, ux, DD);
        mm_big<<<g, 256>>>(Psseq, Fhx, hhat_b,   nx, DD);
    }
    // attention
    attn_logits<<<LL * BB / 8, 256>>>(sseq, u, logits);
    attn_softmax<<<BB, 256>>>(logits, att);

    // persistent AUGRU; init h = sseq[L-1]
    augru2G<<<128, 512, RDSM_BYTES>>>(sseq + (size_t)(LL - 1) * BBDD,
                                      Psseq + (size_t)(LL - 1) * BBDD,
                                      Frh, Fuh, Fhh,
                                      rx, ux, nx, att,
                                      hf, Pp, Phr, ue, out);
}